// round 15
// baseline (speedup 1.0000x reference)
#include <cuda_runtime.h>
#include <cuda_fp16.h>
#include <cstdint>

// Problem constants (N=8192, X=H=Y=1024)
#define NR 8192
#define XD 1024
#define KE2 2048           // [hi | lo*4096] layout for weight operands
#define CHUNKS 128
#define RPC 64
#define LO_SCALE 4096.0f
#define LO_INV   2.44140625e-4f   // 1/4096

// ---------------------------------------------------------------------------
// Device scratch (allocation-free rule)
// ---------------------------------------------------------------------------
__device__ __half g_Xsh [(size_t)NR * XD];    // hi(Xs)
__device__ __half g_WqTe[(size_t)XD * KE2];   // ext [hi|lo*s] of Wq^T
__device__ __half g_WkTe[(size_t)XD * KE2];   // ext [hi|lo*s] of Wk^T
__device__ float  g_Mf[(size_t)XD * XD];      // fp32 M accumulator (split-K atomics)
__device__ __half g_Mh[(size_t)XD * XD];      // hi(M)
__device__ float g_r[NR];                     // fused row-dot accumulators
__device__ float g_e[NR];                     // e_i = u . x_i
__device__ float g_d[NR];                     // d_i = w . x_i
__device__ float g_s[NR];                     // s_i = sum_{j<i} d_j
__device__ float g_part[CHUNKS * XD];
__device__ float g_u[XD];
__device__ float g_w[XD];
__device__ float g_c0;

// ---------------------------------------------------------------------------
// Host-side streams/events for graph fork-join (static init; host-only).
// ---------------------------------------------------------------------------
static cudaStream_t g_s1, g_s2;
static cudaEvent_t g_evRoot, g_evB, g_evC, g_evT;
namespace {
struct StreamInit {
    StreamInit() {
        cudaStreamCreateWithFlags(&g_s1, cudaStreamNonBlocking);
        cudaStreamCreateWithFlags(&g_s2, cudaStreamNonBlocking);
        cudaEventCreateWithFlags(&g_evRoot, cudaEventDisableTiming);
        cudaEventCreateWithFlags(&g_evB,   cudaEventDisableTiming);
        cudaEventCreateWithFlags(&g_evC,   cudaEventDisableTiming);
        cudaEventCreateWithFlags(&g_evT,   cudaEventDisableTiming);
    }
};
StreamInit g_streamInit;
}

// ---------------------------------------------------------------------------
// PTX helpers (base sm_80+ ISA only)
// ---------------------------------------------------------------------------
__device__ __forceinline__ uint32_t smem_u32(const void* p) {
    uint32_t a;
    asm("{ .reg .u64 t; cvta.to.shared.u64 t, %1; cvt.u32.u64 %0, t; }" : "=r"(a) : "l"(p));
    return a;
}
#define CP_ASYNC16(dst, src) \
    asm volatile("cp.async.cg.shared.global [%0], [%1], 16;" :: "r"(dst), "l"(src))
#define CP_COMMIT() asm volatile("cp.async.commit_group;" ::: "memory")
#define CP_WAIT1()  asm volatile("cp.async.wait_group 1;" ::: "memory")
#define CP_WAIT0()  asm volatile("cp.async.wait_group 0;" ::: "memory")

__device__ __forceinline__ void ldsm4(uint32_t& r0, uint32_t& r1, uint32_t& r2,
                                      uint32_t& r3, uint32_t addr) {
    asm volatile("ldmatrix.sync.aligned.m8n8.x4.shared.b16 {%0,%1,%2,%3}, [%4];"
                 : "=r"(r0), "=r"(r1), "=r"(r2), "=r"(r3) : "r"(addr));
}
__device__ __forceinline__ void mma_f16(float* c, uint32_t a0, uint32_t a1,
                                        uint32_t a2, uint32_t a3,
                                        uint32_t b0, uint32_t b1) {
    asm volatile(
        "mma.sync.aligned.m16n8k16.row.col.f32.f16.f16.f32 "
        "{%0,%1,%2,%3}, {%4,%5,%6,%7}, {%8,%9}, {%0,%1,%2,%3};"
        : "+f"(c[0]), "+f"(c[1]), "+f"(c[2]), "+f"(c[3])
        : "r"(a0), "r"(a1), "r"(a2), "r"(a3), "r"(b0), "r"(b1));
}
__device__ __forceinline__ uint32_t swz(uint32_t b) { return b ^ ((b >> 3) & 0x70); }

__device__ __forceinline__ void split1(float v, __half& h, __half& l) {
    h = __float2half_rn(v);
    l = __float2half_rn((v - __half2float(h)) * LO_SCALE);
}

// ---------------------------------------------------------------------------
// fp16 GEMM template. MF = m-frags per warp (16 rows each):
//   MF=4 -> 256x128 block tile, MF=2 -> 128x128 block tile.
// EPI=0 (M-GEMM, split-K): blockIdx.z = khalf, K window [z*nsteps*BK, +nsteps*BK),
//   epilogue atomicAdd fp32 partials into C (pre-zeroed g_Mf).
// EPI=1 (P-GEMM): z=0, nsteps=16, fused row-dot -> atomicAdd into C (g_r).
// BK=64, 3-stage cp.async, one __syncthreads per stage.
// ---------------------------------------------------------------------------
#define BK 64
#define BBY 16384                      // B stage bytes (128 rows)

template <int EPI, int MF>
__global__ void __launch_bounds__(256, 1)
gemm_ext(const __half* __restrict__ A,
         const __half* __restrict__ B,
         float* __restrict__ C,
         const float* __restrict__ xx,
         int ldk, int nsteps) {
    constexpr int RT  = MF * 64;       // block rows
    constexpr int ABY = RT * BK * 2;   // A stage bytes
    constexpr int STB = ABY + BBY;

    extern __shared__ char smem_raw[];
    __shared__ float red[256];
    uint32_t raw = smem_u32(smem_raw);
    uint32_t ab = (raw + 1023u) & ~1023u;

    const int tid = threadIdx.x;
    const int wid = tid >> 5;
    const int lane = tid & 31;
    const int m0 = blockIdx.y * RT;
    const int n0 = blockIdx.x * 128;
    const int koff = (EPI == 0) ? (blockIdx.z * nsteps * BK) : 0;
    const int wm = (wid & 3) * (MF * 16);
    const int wn = (wid >> 2) * 64;

    const __half* gA = A + (size_t)m0 * ldk + koff;
    const __half* gB = B + (size_t)n0 * ldk + koff;

    float acc[MF][8][4];
    #pragma unroll
    for (int i = 0; i < MF; i++)
        #pragma unroll
        for (int j = 0; j < 8; j++)
            #pragma unroll
            for (int q = 0; q < 4; q++) acc[i][j][q] = 0.f;

    const int lrow = tid >> 3;
    const int lc16 = tid & 7;
    auto issue = [&](int s, int buf) {
        const uint32_t sa = ab + buf * STB;
        const uint32_t sb = sa + ABY;
        const int kb = s * BK;
        #pragma unroll
        for (int i = 0; i < RT / 32; i++) {
            int row = lrow + i * 32;
            uint32_t so = swz((uint32_t)(row * 128 + lc16 * 16));
            CP_ASYNC16(sa + so, gA + (size_t)row * ldk + kb + lc16 * 8);
        }
        #pragma unroll
        for (int i = 0; i < 4; i++) {
            int row = lrow + i * 32;
            uint32_t so = swz((uint32_t)(row * 128 + lc16 * 16));
            CP_ASYNC16(sb + so, gB + (size_t)row * ldk + kb + lc16 * 8);
        }
        CP_COMMIT();
    };
    issue(0, 0);
    issue(1, 1);

    const int lr = lane & 15;
    const int lc = lane >> 4;

    int buf = 0;
    for (int s = 0; s < nsteps; s++) {
        if (s + 1 < nsteps) { CP_WAIT1(); } else { CP_WAIT0(); }
        __syncthreads();
        if (s + 2 < nsteps) {
            int nb2 = buf + 2; if (nb2 >= 3) nb2 -= 3;
            issue(s + 2, nb2);
        }
        const uint32_t sa = ab + buf * STB;
        const uint32_t sb = sa + ABY;
        #pragma unroll
        for (int s4 = 0; s4 < 4; s4++) {
            const int xcol = s4 * 32 + lc * 16;
            uint32_t a[MF][4];
            #pragma unroll
            for (int mm = 0; mm < MF; mm++) {
                int row = wm + mm * 16 + lr;
                uint32_t addr = sa + row * 128 + (xcol ^ ((row & 7) * 16));
                ldsm4(a[mm][0], a[mm][1], a[mm][2], a[mm][3], addr);
            }
            #pragma unroll
            for (int nb = 0; nb < 4; nb++) {
                int row = wn + nb * 16 + lr;
                uint32_t addr = sb + row * 128 + (xcol ^ ((row & 7) * 16));
                uint32_t b0, b1, b2, b3;
                ldsm4(b0, b1, b2, b3, addr);
                #pragma unroll
                for (int mm = 0; mm < MF; mm++) {
                    mma_f16(acc[mm][2 * nb],     a[mm][0], a[mm][1], a[mm][2], a[mm][3], b0, b2);
                    mma_f16(acc[mm][2 * nb + 1], a[mm][0], a[mm][1], a[mm][2], a[mm][3], b1, b3);
                }
            }
        }
        if (++buf == 3) buf = 0;
    }

    const int qr = lane >> 2;
    const int qc = (lane & 3) * 2;

    if (EPI == 0) {
        // split-K partial: atomicAdd into fp32 M accumulator
        #pragma unroll
        for (int mm = 0; mm < MF; mm++) {
            int r = m0 + wm + mm * 16 + qr;
            #pragma unroll
            for (int j = 0; j < 8; j++) {
                int c = n0 + wn + j * 8 + qc;
                atomicAdd(&C[(size_t)r * XD + c],           acc[mm][j][0]);
                atomicAdd(&C[(size_t)r * XD + c + 1],       acc[mm][j][1]);
                atomicAdd(&C[(size_t)(r + 8) * XD + c],     acc[mm][j][2]);
                atomicAdd(&C[(size_t)(r + 8) * XD + c + 1], acc[mm][j][3]);
            }
        }
    } else {
        // fused row-dot: g_r[i] += sum_c x[i][c] * P_tile[i][c]
        float pr[2 * MF];
        #pragma unroll
        for (int q = 0; q < 2 * MF; q++) pr[q] = 0.f;
        #pragma unroll
        for (int mm = 0; mm < MF; mm++) {
            int r = m0 + wm + mm * 16 + qr;
            #pragma unroll
            for (int j = 0; j < 8; j++) {
                int c = n0 + wn + j * 8 + qc;
                float2 x0 = *(const float2*)&xx[(size_t)r * XD + c];
                float2 x1 = *(const float2*)&xx[(size_t)(r + 8) * XD + c];
                pr[2 * mm]     += acc[mm][j][0] * x0.x + acc[mm][j][1] * x0.y;
                pr[2 * mm + 1] += acc[mm][j][2] * x1.x + acc[mm][j][3] * x1.y;
            }
        }
        #pragma unroll
        for (int q = 0; q < 2 * MF; q++) {
            pr[q] += __shfl_xor_sync(0xFFFFFFFFu, pr[q], 1);
            pr[q] += __shfl_xor_sync(0xFFFFFFFFu, pr[q], 2);
        }
        red[tid] = 0.f;
        __syncthreads();
        if ((lane & 3) == 0) {
            #pragma unroll
            for (int mm = 0; mm < MF; mm++) {
                atomicAdd(&red[wm + mm * 16 + qr],     pr[2 * mm]);
                atomicAdd(&red[wm + mm * 16 + qr + 8], pr[2 * mm + 1]);
            }
        }
        __syncthreads();
        atomicAdd(&C[m0 + tid], red[tid]);
    }
}

#define GS4 (1024 + 3 * (256 * BK * 2 + BBY))   // 256-tile smem
#define GS2 (1024 + 3 * (128 * BK * 2 + BBY))   // 128-tile smem

// ---------------------------------------------------------------------------
// Transpose + fp16 hi/lo split for Wq and Wk (blockIdx.z selects), FUSED with
// u = Wq^T bk (z=0) / w = Wk^T bq (z=1).
// ---------------------------------------------------------------------------
__global__ void transpose_ext_uw(const float* __restrict__ in0, __half* __restrict__ out0,
                                 const float* __restrict__ in1, __half* __restrict__ out1,
                                 const float* __restrict__ bk, const float* __restrict__ bq) {
    __shared__ float t[32][33];
    __shared__ float pd[8][32];
    const int z = blockIdx.z;
    const float* in = z ? in1 : in0;
    __half* out = z ? out1 : out0;
    const float* bvec = z ? bq : bk;
    float* uw = z ? g_w : g_u;
    int bx = blockIdx.x * 32, by = blockIdx.y * 32;
    int tx = threadIdx.x, ty = threadIdx.y;
    #pragma unroll
    for (int j = 0; j < 32; j += 8)
        t[ty + j][tx] = in[(size_t)(by + ty + j) * XD + bx + tx];
    __syncthreads();
    {
        float s = 0.f;
        #pragma unroll
        for (int k = 0; k < 4; k++)
            s += t[ty * 4 + k][tx] * bvec[by + ty * 4 + k];
        pd[ty][tx] = s;
    }
    #pragma unroll
    for (int j = 0; j < 32; j += 8) {
        float v = t[tx][ty + j];
        __half h, l;
        split1(v, h, l);
        size_t r = bx + ty + j;
        int c = by + tx;
        out[r * KE2 + c]      = h;
        out[r * KE2 + XD + c] = l;
    }
    __syncthreads();
    if (ty == 0) {
        float s = 0.f;
        #pragma unroll
        for (int q = 0; q < 8; q++) s += pd[q][tx];
        atomicAdd(&uw[bx + tx], s);
    }
}

// ---------------------------------------------------------------------------
// Scan: per-chunk column sums, then writeXs computes offsets inline (hi only)
// ---------------------------------------------------------------------------
__global__ void colsum_kernel(const float* __restrict__ x) {
    int col = blockIdx.x * 256 + threadIdx.x;
    int ch  = blockIdx.y;
    const float* p = x + (size_t)ch * RPC * XD + col;
    float s0 = 0.f, s1 = 0.f;
    #pragma unroll 8
    for (int r = 0; r < RPC; r += 2) {
        s0 += p[(size_t)r * XD];
        s1 += p[(size_t)(r + 1) * XD];
    }
    g_part[ch * XD + col] = s0 + s1;
}
__global__ void writeXs_hi(const float* __restrict__ x) {
    int col = blockIdx.x * 256 + threadIdx.x;
    int ch  = blockIdx.y;
    int flat = (ch * gridDim.x + blockIdx.x) * 256 + threadIdx.x;
    if (flat < NR) g_r[flat] = 0.f;
    float run = 0.f;
    for (int c = 0; c < ch; c++) run += g_part[c * XD + col];
    #pragma unroll 4
    for (int r = 0; r < RPC; r++) {
        size_t row = (size_t)ch * RPC + r;
        g_Xsh[row * XD + col] = __float2half_rn(run);
        run += x[row * XD + col];
    }
}

// ---------------------------------------------------------------------------
// Zero u/w + Mf, compute c0 = bq.bk (grid 1024; runs before the transpose)
// ---------------------------------------------------------------------------
__global__ void zero_all(const float* __restrict__ bq, const float* __restrict__ bk) {
    int t = blockIdx.x * 256 + threadIdx.x;           // 1024*256 threads
    *(float4*)&g_Mf[(size_t)t * 4] = make_float4(0.f, 0.f, 0.f, 0.f);
    if (t < XD) { g_u[t] = 0.f; g_w[t] = 0.f; }
    if (blockIdx.x == 0 && threadIdx.x < 32) {
        float s = 0.f;
        for (int i = threadIdx.x; i < XD; i += 32) s += bq[i] * bk[i];
        #pragma unroll
        for (int off = 16; off > 0; off >>= 1)
            s += __shfl_xor_sync(0xFFFFFFFFu, s, off);
        if (threadIdx.x == 0) g_c0 = s;
    }
}

// ---------------------------------------------------------------------------
// Convert fp32 M accumulator -> hi(M) fp16
// ---------------------------------------------------------------------------
__global__ void mconv_hi(__half* __restrict__ out) {
    const size_t i = (size_t)(blockIdx.x * 256 + threadIdx.x) * 4;
    float4 v = *(const float4*)&g_Mf[i];
    __half2 h0 = __floats2half2_rn(v.x, v.y);
    __half2 h1 = __floats2half2_rn(v.z, v.w);
    *(__half2*)&out[i]     = h0;
    *(__half2*)&out[i + 2] = h1;
}

// ---------------------------------------------------------------------------
// Per-row dots: e_i = u.x_i, d_i = w.x_i
// ---------------------------------------------------------------------------
__global__ void rowdots_kernel(const float* __restrict__ x) {
    const int i = blockIdx.x;
    const int tid = threadIdx.x;
    float4 xv = *(const float4*)&x[(size_t)i * XD + tid * 4];
    float4 uv = *(const float4*)&g_u[tid * 4];
    float4 wv = *(const float4*)&g_w[tid * 4];
    float e = xv.x * uv.x + xv.y * uv.y + xv.z * uv.z + xv.w * uv.w;
    float d = xv.x * wv.x + xv.y * wv.y + xv.z * wv.z + xv.w * wv.w;
    #pragma unroll
    for (int off = 16; off > 0; off >>= 1) {
        e += __shfl_xor_sync(0xFFFFFFFFu, e, off);
        d += __shfl_xor_sync(0xFFFFFFFFu, d, off);
    }
    __shared__ float se[8], sd[8];
    if ((tid & 31) == 0) { se[tid >> 5] = e; sd[tid >> 5] = d; }
    __syncthreads();
    if (tid == 0) {
        float te = 0.f, td = 0.f;
        #pragma unroll
        for (int q = 0; q < 8; q++) { te += se[q]; td += sd[q]; }
        g_e[i] = te;
        g_d[i] = td;
    }
}

// ---------------------------------------------------------------------------
// Exclusive scan of d (8192 scalars) -> s, shfl-based
// ---------------------------------------------------------------------------
__global__ void dscan_kernel() {
    const int t = threadIdx.x;
    const int lane = t & 31;
    const int warp = t >> 5;
    float v[8];
    float sum = 0.f;
    #pragma unroll
    for (int k = 0; k < 8; k++) { v[k] = g_d[t * 8 + k]; sum += v[k]; }
    float sc = sum;
    #pragma unroll
    for (int off = 1; off < 32; off <<= 1) {
        float n = __shfl_up_sync(0xFFFFFFFFu, sc, off);
        if (lane >= off) sc += n;
    }
    __shared__ float wsum[32];
    if (lane == 31) wsum[warp] = sc;
    __syncthreads();
    if (warp == 0) {
        float ws = wsum[lane];
        #pragma unroll
        for (int off = 1; off < 32; off <<= 1) {
            float n = __shfl_up_sync(0xFFFFFFFFu, ws, off);
            if (lane >= off) ws += n;
        }
        wsum[lane] = ws;
    }
    __syncthreads();
    float run = (warp ? wsum[warp - 1] : 0.f) + (sc - sum);
    #pragma unroll
    for (int k = 0; k < 8; k++) {
        g_s[t * 8 + k] = run;
        run += v[k];
    }
}

// ---------------------------------------------------------------------------
// Finalize: out[i,:] = g_r[i] + i*(e_i + c0) + s_i
// ---------------------------------------------------------------------------
__global__ void finalize_kernel(float* __restrict__ out) {
    const int i = blockIdx.x;
    const float r = g_r[i] + (float)i * (g_e[i] + g_c0) + g_s[i];
    float4 rv = make_float4(r, r, r, r);
    *(float4*)&out[(size_t)i * XD + threadIdx.x * 4] = rv;
}

// ---------------------------------------------------------------------------
// kernel_launch — inputs: x, Wk, bk, Wv, bv, Wq, bq  (Wv/bv unused: V:=ones)
// Fork-join DAG:
//   stream0: zero_all → transpose(+u/w) → evT → M-GEMM(splitK z=2, atomics)
//            → mconv ────────────────────────────────────────────────┐
//   s1:      colsum → writeXs (zeroes g_r) ───────────────────── evB ┤→ P-GEMM → finalize
//   s2:      wait evT → rowdots → dscan ─────────────────────── evC ─┘  (needs evC)
// ---------------------------------------------------------------------------
extern "C" void kernel_launch(void* const* d_in, const int* in_sizes, int n_in,
                              void* d_out, int out_size) {
    const float* x  = (const float*)d_in[0];
    const float* Wk = (const float*)d_in[1];
    const float* bk = (const float*)d_in[2];
    const float* Wq = (const float*)d_in[5];
    const float* bq = (const float*)d_in[6];
    float* out = (float*)d_out;

    __half *Xsh, *Mh, *WqTe, *WkTe;
    float *Mf, *r;
    cudaGetSymbolAddress((void**)&Xsh,  g_Xsh);
    cudaGetSymbolAddress((void**)&Mh,   g_Mh);
    cudaGetSymbolAddress((void**)&WqTe, g_WqTe);
    cudaGetSymbolAddress((void**)&WkTe, g_WkTe);
    cudaGetSymbolAddress((void**)&Mf,   g_Mf);
    cudaGetSymbolAddress((void**)&r,    g_r);

    cudaFuncSetAttribute(gemm_ext<0, 2>, cudaFuncAttributeMaxDynamicSharedMemorySize, GS2);
    cudaFuncSetAttribute(gemm_ext<1, 4>, cudaFuncAttributeMaxDynamicSharedMemorySize, GS4);

    // Fork
    cudaEventRecord(g_evRoot, 0);
    cudaStreamWaitEvent(g_s1, g_evRoot, 0);
    cudaStreamWaitEvent(g_s2, g_evRoot, 0);

    // Chain B (s1): prefix sum of x -> hi(Xs); also zeroes g_r
    colsum_kernel<<<dim3(XD / 256, CHUNKS), 256, 0, g_s1>>>(x);
    writeXs_hi<<<dim3(XD / 256, CHUNKS), 256, 0, g_s1>>>(x);
    cudaEventRecord(g_evB, g_s1);

    // Chain A (stream 0): zero Mf/u/w + c0, fused transpose (+u/w),
    // split-K M-GEMM (128 CTAs, fp32 atomics), convert -> hi(M)
    zero_all<<<1024, 256>>>(bq, bk);
    transpose_ext_uw<<<dim3(32, 32, 2), dim3(32, 8)>>>(Wq, WqTe, Wk, WkTe, bk, bq);
    cudaEventRecord(g_evT, 0);
    gemm_ext<0, 2><<<dim3(XD / 128, XD / 128, 2), 256, GS2>>>(WqTe, WkTe, Mf, nullptr, KE2, 8);
    mconv_hi<<<1024, 256>>>(Mh);

    // Chain C (s2): waits for u/w, then per-row dots + scalar scan of d
    cudaStreamWaitEvent(g_s2, g_evT, 0);
    rowdots_kernel<<<NR, 256, 0, g_s2>>>(x);
    dscan_kernel<<<1, 1024, 0, g_s2>>>();
    cudaEventRecord(g_evC, g_s2);

    // Join B, then fused P-GEMM + row-dot (single hi*hi pass)
    cudaStreamWaitEvent(0, g_evB, 0);
    gemm_ext<1, 4><<<dim3(XD / 128, NR / 256, 1), 256, GS4>>>(Xsh, Mh, r, x, XD, 16);

    // Join C, then broadcast
    cudaStreamWaitEvent(0, g_evC, 0);
    finalize_kernel<<<NR, 256>>>(out);
}